// round 1
// baseline (speedup 1.0000x reference)
#include <cuda_runtime.h>
#include <cuda_bf16.h>
#include <cstdint>

// ---------------------------------------------------------------------------
// MPS contraction:  out = stack([Re, Im]) of  left[x0] . B[x1]...B[x62] . right[x63]
// N=131072 samples, L=64 sites, d=2 choices, D=16 bond dim, complex fp32.
//
// Strategy: precompute all 2^6=64 products of 6 consecutive bulk matrices (G6),
// 128 fused start vectors LG = left[s0].B.B.B.B.B.B, and 8 fused end vectors
// R2 = B.B.right. Each sample then does 9 register-resident complex matvecs
// (matrix streamed from shared memory) + 1 dot product.
// Bit convention: LSB-first within a group, so table index = (bits>>off)&mask.
// ---------------------------------------------------------------------------

#define DB 16   // bond dimension

__device__ float2 g_G2[4  * 256];   // B[t0].B[t1]
__device__ float2 g_G4[16 * 256];   // G2.G2
__device__ float2 g_G6[64 * 256];   // G4.G2
__device__ float2 g_LG[128 * 16];   // left[s0].G6
__device__ float2 g_R2[8   * 16];   // G2.right[t2]

// ----------------------------- prep kernels --------------------------------

__global__ void k_g2(const float* __restrict__ br, const float* __restrict__ bi) {
    int c = blockIdx.x;                 // 0..3 : t0 = c&1 applied first
    int e = threadIdx.x;                // 0..255
    int i = e >> 4, j = e & 15;
    const float* Ar = br + (c & 1) * 256;
    const float* Ai = bi + (c & 1) * 256;
    const float* Br = br + ((c >> 1) & 1) * 256;
    const float* Bi = bi + ((c >> 1) & 1) * 256;
    float rr = 0.f, ri = 0.f;
    #pragma unroll
    for (int k = 0; k < 16; k++) {
        float ar = Ar[i * 16 + k], ai = Ai[i * 16 + k];
        float bre = Br[k * 16 + j], bim = Bi[k * 16 + j];
        rr += ar * bre - ai * bim;
        ri += ar * bim + ai * bre;
    }
    g_G2[c * 256 + e] = make_float2(rr, ri);
}

__global__ void k_g4() {
    int c = blockIdx.x;                 // 0..15
    int e = threadIdx.x;
    int i = e >> 4, j = e & 15;
    const float2* A = g_G2 + (c & 3) * 256;         // first 2 spins
    const float2* B = g_G2 + ((c >> 2) & 3) * 256;  // last 2 spins
    float rr = 0.f, ri = 0.f;
    #pragma unroll
    for (int k = 0; k < 16; k++) {
        float2 a = A[i * 16 + k], b = B[k * 16 + j];
        rr += a.x * b.x - a.y * b.y;
        ri += a.x * b.y + a.y * b.x;
    }
    g_G4[c * 256 + e] = make_float2(rr, ri);
}

__global__ void k_g6() {
    int c = blockIdx.x;                 // 0..63
    int e = threadIdx.x;
    int i = e >> 4, j = e & 15;
    const float2* A = g_G4 + (c & 15) * 256;        // first 4 spins
    const float2* B = g_G2 + ((c >> 4) & 3) * 256;  // last 2 spins
    float rr = 0.f, ri = 0.f;
    #pragma unroll
    for (int k = 0; k < 16; k++) {
        float2 a = A[i * 16 + k], b = B[k * 16 + j];
        rr += a.x * b.x - a.y * b.y;
        ri += a.x * b.y + a.y * b.x;
    }
    g_G6[c * 256 + e] = make_float2(rr, ri);
}

__global__ void k_lg(const float* __restrict__ lr, const float* __restrict__ li) {
    int e = blockIdx.x * 1024 + threadIdx.x;  // 0..2047
    if (e >= 128 * 16) return;
    int c = e >> 4, j = e & 15;
    int s0 = c & 1;                              // left selector = bit 0
    const float2* G = g_G6 + ((c >> 1) & 63) * 256;
    float rr = 0.f, ri = 0.f;
    #pragma unroll
    for (int k = 0; k < 16; k++) {
        float ar = lr[s0 * 16 + k], ai = li[s0 * 16 + k];
        float2 b = G[k * 16 + j];
        rr += ar * b.x - ai * b.y;
        ri += ar * b.y + ai * b.x;
    }
    g_LG[c * 16 + j] = make_float2(rr, ri);
}

__global__ void k_r2(const float* __restrict__ rr_, const float* __restrict__ ri_) {
    int e = threadIdx.x;                 // 0..127
    int c = e >> 4, i = e & 15;
    const float2* A = g_G2 + (c & 3) * 256;   // spins 61,62
    int t2 = (c >> 2) & 1;                    // right selector
    float rr = 0.f, ri = 0.f;
    #pragma unroll
    for (int k = 0; k < 16; k++) {
        float2 a = A[i * 16 + k];
        float bre = rr_[t2 * 16 + k], bim = ri_[t2 * 16 + k];
        rr += a.x * bre - a.y * bim;
        ri += a.x * bim + a.y * bre;
    }
    g_R2[c * 16 + i] = make_float2(rr, ri);
}

// ------------------------------ main kernel --------------------------------

// SMEM layout (floats). Each 16x16 complex matrix = 512 floats, skewed by
// 4 floats (16B) so the 64 matrices don't alias into the same bank columns.
constexpr int MAT_STRIDE  = 516;
constexpr int LG_BASE     = 64 * MAT_STRIDE;          // 33024
constexpr int R2_BASE     = LG_BASE + 128 * 32;       // 37120
constexpr int SMEM_FLOATS = R2_BASE + 8 * 32;         // 37376 -> 149504 B

__global__ __launch_bounds__(512)
void mps_main(const int* __restrict__ x, float* __restrict__ out, int N) {
    extern __shared__ float sm[];

    // Stage tables into shared memory.
    {
        const float* g6f = (const float*)g_G6;
        for (int idx = threadIdx.x; idx < 64 * 512; idx += 512)
            sm[(idx >> 9) * MAT_STRIDE + (idx & 511)] = g6f[idx];
        const float* lgf = (const float*)g_LG;
        for (int idx = threadIdx.x; idx < 128 * 32; idx += 512)
            sm[LG_BASE + idx] = lgf[idx];
        const float* r2f = (const float*)g_R2;
        for (int idx = threadIdx.x; idx < 8 * 32; idx += 512)
            sm[R2_BASE + idx] = r2f[idx];
    }
    __syncthreads();

    int n = blockIdx.x * 512 + threadIdx.x;

    // Pack the 64 spins of this sample into one u64 (bit l = x[n][l]).
    const int4* xr = (const int4*)(x + (size_t)n * 64);
    unsigned long long bits = 0ull;
    #pragma unroll
    for (int q = 0; q < 16; q++) {
        int4 v = xr[q];
        unsigned nib = (unsigned)((v.x & 1) | ((v.y & 1) << 1) |
                                  ((v.z & 1) << 2) | ((v.w & 1) << 3));
        bits |= (unsigned long long)nib << (q * 4);
    }

    // Start vector: LG[bits 0..6]  (left selector + first 6 bulk spins).
    float vr[16], vi[16];
    {
        const float* L = sm + LG_BASE + (int)(bits & 127) * 32;
        #pragma unroll
        for (int j = 0; j < 16; j++) { vr[j] = L[2 * j]; vi[j] = L[2 * j + 1]; }
    }

    // 9 rounds of 6 fused bulk steps: spins 7..60.
    #pragma unroll 1
    for (int r = 0; r < 9; r++) {
        int s = (int)(bits >> (7 + 6 * r)) & 63;
        const float4* M = (const float4*)(sm + s * MAT_STRIDE);
        float ar[16], ai[16];
        #pragma unroll
        for (int j = 0; j < 16; j++) { ar[j] = 0.f; ai[j] = 0.f; }
        #pragma unroll
        for (int i = 0; i < 16; i++) {
            float xre = vr[i], xim = vi[i];
            #pragma unroll
            for (int j4 = 0; j4 < 8; j4++) {
                float4 m = M[i * 8 + j4];   // (Mr[2j], Mi[2j], Mr[2j+1], Mi[2j+1])
                ar[2 * j4]     = fmaf(xre, m.x, fmaf(-xim, m.y, ar[2 * j4]));
                ai[2 * j4]     = fmaf(xre, m.y, fmaf( xim, m.x, ai[2 * j4]));
                ar[2 * j4 + 1] = fmaf(xre, m.z, fmaf(-xim, m.w, ar[2 * j4 + 1]));
                ai[2 * j4 + 1] = fmaf(xre, m.w, fmaf( xim, m.z, ai[2 * j4 + 1]));
            }
        }
        #pragma unroll
        for (int j = 0; j < 16; j++) { vr[j] = ar[j]; vi[j] = ai[j]; }
    }

    // Final contraction: spins 61,62 + right selector (bit 63).
    {
        const float* R = sm + R2_BASE + (int)((bits >> 61) & 7) * 32;
        float sr = 0.f, si = 0.f;
        #pragma unroll
        for (int i = 0; i < 16; i++) {
            float rre = R[2 * i], rim = R[2 * i + 1];
            sr = fmaf(vr[i], rre, fmaf(-vi[i], rim, sr));
            si = fmaf(vr[i], rim, fmaf( vi[i], rre, si));
        }
        out[n]     = sr;
        out[N + n] = si;
    }
}

// ------------------------------ launch -------------------------------------

extern "C" void kernel_launch(void* const* d_in, const int* in_sizes, int n_in,
                              void* d_out, int out_size) {
    const int*   x       = (const int*)  d_in[0];
    const float* left_r  = (const float*)d_in[1];
    const float* left_i  = (const float*)d_in[2];
    const float* bulk_r  = (const float*)d_in[3];
    const float* bulk_i  = (const float*)d_in[4];
    const float* right_r = (const float*)d_in[5];
    const float* right_i = (const float*)d_in[6];

    int N = in_sizes[0] / 64;   // 131072

    k_g2<<<4, 256>>>(bulk_r, bulk_i);
    k_g4<<<16, 256>>>();
    k_g6<<<64, 256>>>();
    k_lg<<<2, 1024>>>(left_r, left_i);
    k_r2<<<1, 128>>>(right_r, right_i);

    cudaFuncSetAttribute(mps_main, cudaFuncAttributeMaxDynamicSharedMemorySize,
                         SMEM_FLOATS * (int)sizeof(float));
    mps_main<<<N / 512, 512, SMEM_FLOATS * sizeof(float)>>>(x, (float*)d_out, N);
}

// round 2
// speedup vs baseline: 1.1116x; 1.1116x over previous
#include <cuda_runtime.h>
#include <cuda_bf16.h>
#include <cstdint>

// ---------------------------------------------------------------------------
// MPS contraction:  out = stack([Re, Im]) of  left[x0] . B[x1]...B[x62] . right[x63]
// N=131072, L=64, d=2, D=16, complex fp32.
//
// R2 strategy: LG12 table (left + 12 spins, 2^13 vectors, 1MB, L2) +
// 6 rounds of G6 (64 six-step products, SMEM) + R14 table (14 spins + right,
// 2^15 vectors, 4MB, L2). Bit l of the packed word = x[n][l], LSB-first.
// ---------------------------------------------------------------------------

__device__ float2 g_G2[4  * 256];    // B[t0].B[t1]          (t0 applied first = LSB)
__device__ float2 g_G4[16 * 256];    // G2.G2
__device__ float2 g_G6[64 * 256];    // G4.G2
__device__ float2 g_LG6[128 * 16];   // left[b0].G6[b1..6]
__device__ float2 g_LG12[8192 * 16]; // LG6[b0..6].G6[b7..12]        (1 MB)
__device__ float2 g_R2[8 * 16];      // G2.right
__device__ float2 g_R8[512 * 16];    // G6[b0..5].R2[b6..8]
__device__ float2 g_R14[32768 * 16]; // G6[b0..5].R8[b6..14]         (4 MB)

// ----------------------------- prep kernels --------------------------------

__global__ void k_g2(const float* __restrict__ br, const float* __restrict__ bi) {
    int c = blockIdx.x, e = threadIdx.x;
    int i = e >> 4, j = e & 15;
    const float* Ar = br + (c & 1) * 256;
    const float* Ai = bi + (c & 1) * 256;
    const float* Br = br + ((c >> 1) & 1) * 256;
    const float* Bi = bi + ((c >> 1) & 1) * 256;
    float rr = 0.f, ri = 0.f;
    #pragma unroll
    for (int k = 0; k < 16; k++) {
        float ar = Ar[i * 16 + k], ai = Ai[i * 16 + k];
        float bre = Br[k * 16 + j], bim = Bi[k * 16 + j];
        rr += ar * bre - ai * bim;
        ri += ar * bim + ai * bre;
    }
    g_G2[c * 256 + e] = make_float2(rr, ri);
}

__global__ void k_g4() {
    int c = blockIdx.x, e = threadIdx.x;
    int i = e >> 4, j = e & 15;
    const float2* A = g_G2 + (c & 3) * 256;
    const float2* B = g_G2 + ((c >> 2) & 3) * 256;
    float rr = 0.f, ri = 0.f;
    #pragma unroll
    for (int k = 0; k < 16; k++) {
        float2 a = A[i * 16 + k], b = B[k * 16 + j];
        rr += a.x * b.x - a.y * b.y;
        ri += a.x * b.y + a.y * b.x;
    }
    g_G4[c * 256 + e] = make_float2(rr, ri);
}

__global__ void k_g6() {
    int c = blockIdx.x, e = threadIdx.x;
    int i = e >> 4, j = e & 15;
    const float2* A = g_G4 + (c & 15) * 256;
    const float2* B = g_G2 + ((c >> 4) & 3) * 256;
    float rr = 0.f, ri = 0.f;
    #pragma unroll
    for (int k = 0; k < 16; k++) {
        float2 a = A[i * 16 + k], b = B[k * 16 + j];
        rr += a.x * b.x - a.y * b.y;
        ri += a.x * b.y + a.y * b.x;
    }
    g_G6[c * 256 + e] = make_float2(rr, ri);
}

__global__ void k_lg6(const float* __restrict__ lr, const float* __restrict__ li) {
    int e = blockIdx.x * 1024 + threadIdx.x;
    if (e >= 128 * 16) return;
    int c = e >> 4, j = e & 15;
    int s0 = c & 1;
    const float2* G = g_G6 + ((c >> 1) & 63) * 256;
    float rr = 0.f, ri = 0.f;
    #pragma unroll
    for (int k = 0; k < 16; k++) {
        float ar = lr[s0 * 16 + k], ai = li[s0 * 16 + k];
        float2 b = G[k * 16 + j];
        rr += ar * b.x - ai * b.y;
        ri += ar * b.y + ai * b.x;
    }
    g_LG6[c * 16 + j] = make_float2(rr, ri);
}

// LG12[c] = LG6[c&127] (row-vec) * G6[(c>>7)&63]
__global__ void k_lg12() {
    int e = blockIdx.x * 256 + threadIdx.x;   // 0..131071
    int c = e >> 4, j = e & 15;
    const float2* V = g_LG6 + (c & 127) * 16;
    const float2* G = g_G6 + ((c >> 7) & 63) * 256;
    float rr = 0.f, ri = 0.f;
    #pragma unroll
    for (int k = 0; k < 16; k++) {
        float2 v = V[k], b = G[k * 16 + j];
        rr += v.x * b.x - v.y * b.y;
        ri += v.x * b.y + v.y * b.x;
    }
    g_LG12[c * 16 + j] = make_float2(rr, ri);
}

__global__ void k_r2(const float* __restrict__ rr_, const float* __restrict__ ri_) {
    int e = threadIdx.x;                 // 0..127
    int c = e >> 4, i = e & 15;
    const float2* A = g_G2 + (c & 3) * 256;
    int t2 = (c >> 2) & 1;
    float rr = 0.f, ri = 0.f;
    #pragma unroll
    for (int k = 0; k < 16; k++) {
        float2 a = A[i * 16 + k];
        float bre = rr_[t2 * 16 + k], bim = ri_[t2 * 16 + k];
        rr += a.x * bre - a.y * bim;
        ri += a.x * bim + a.y * bre;
    }
    g_R2[c * 16 + i] = make_float2(rr, ri);
}

// R8[c] = G6[c&63] * R2[(c>>6)&7]   (column vector)
__global__ void k_r8() {
    int e = blockIdx.x * 256 + threadIdx.x;   // 0..8191
    int c = e >> 4, i = e & 15;
    const float2* G = g_G6 + (c & 63) * 256;
    const float2* V = g_R2 + ((c >> 6) & 7) * 16;
    float rr = 0.f, ri = 0.f;
    #pragma unroll
    for (int k = 0; k < 16; k++) {
        float2 a = G[i * 16 + k], v = V[k];
        rr += a.x * v.x - a.y * v.y;
        ri += a.x * v.y + a.y * v.x;
    }
    g_R8[c * 16 + i] = make_float2(rr, ri);
}

// R14[c] = G6[c&63] * R8[(c>>6)&511]
__global__ void k_r14() {
    int e = blockIdx.x * 256 + threadIdx.x;   // 0..524287
    int c = e >> 4, i = e & 15;
    const float2* G = g_G6 + (c & 63) * 256;
    const float2* V = g_R8 + ((c >> 6) & 511) * 16;
    float rr = 0.f, ri = 0.f;
    #pragma unroll
    for (int k = 0; k < 16; k++) {
        float2 a = G[i * 16 + k], v = V[k];
        rr += a.x * v.x - a.y * v.y;
        ri += a.x * v.y + a.y * v.x;
    }
    g_R14[c * 16 + i] = make_float2(rr, ri);
}

// ------------------------------ main kernel --------------------------------

// 16B skew per matrix: stride 516 floats = 129 quads, 129 mod 8 = 1 ->
// matrix s maps to bank-quad class (s mod 8): max spread for 16B loads.
constexpr int MAT_STRIDE  = 516;
constexpr int SMEM_FLOATS = 64 * MAT_STRIDE;   // 33024 floats = 132096 B

__global__ __launch_bounds__(512)
void mps_main(const int* __restrict__ x, float* __restrict__ out, int N) {
    extern __shared__ float sm[];

    {   // stage G6 into SMEM
        const float* g6f = (const float*)g_G6;
        for (int idx = threadIdx.x; idx < 64 * 512; idx += 512)
            sm[(idx >> 9) * MAT_STRIDE + (idx & 511)] = g6f[idx];
    }
    __syncthreads();

    int n = blockIdx.x * 512 + threadIdx.x;

    // Pack 64 spins into one u64 (bit l = x[n][l]).
    const int4* xr = (const int4*)(x + (size_t)n * 64);
    unsigned long long bits = 0ull;
    #pragma unroll
    for (int q = 0; q < 16; q++) {
        int4 v = xr[q];
        unsigned nib = (unsigned)((v.x & 1) | ((v.y & 1) << 1) |
                                  ((v.z & 1) << 2) | ((v.w & 1) << 3));
        bits |= (unsigned long long)nib << (q * 4);
    }

    // Start vector: LG12[bits 0..12]  (from L2-resident table).
    float vr[16], vi[16];
    {
        const float4* L = (const float4*)(g_LG12 + (size_t)(bits & 8191) * 16);
        #pragma unroll
        for (int q = 0; q < 8; q++) {
            float4 v = L[q];
            vr[2 * q] = v.x; vi[2 * q] = v.y;
            vr[2 * q + 1] = v.z; vi[2 * q + 1] = v.w;
        }
    }

    // 6 rounds of 6 fused bulk steps: spins 13..48.
    #pragma unroll 1
    for (int r = 0; r < 6; r++) {
        int s = (int)(bits >> (13 + 6 * r)) & 63;
        const float4* M = (const float4*)(sm + s * MAT_STRIDE);
        float ar[16], ai[16];
        #pragma unroll
        for (int j = 0; j < 16; j++) { ar[j] = 0.f; ai[j] = 0.f; }
        #pragma unroll
        for (int i = 0; i < 16; i++) {
            float xre = vr[i], xim = vi[i];
            #pragma unroll
            for (int j4 = 0; j4 < 8; j4++) {
                float4 m = M[i * 8 + j4];   // (Mr[2j], Mi[2j], Mr[2j+1], Mi[2j+1])
                ar[2 * j4]     = fmaf(xre, m.x, fmaf(-xim, m.y, ar[2 * j4]));
                ai[2 * j4]     = fmaf(xre, m.y, fmaf( xim, m.x, ai[2 * j4]));
                ar[2 * j4 + 1] = fmaf(xre, m.z, fmaf(-xim, m.w, ar[2 * j4 + 1]));
                ai[2 * j4 + 1] = fmaf(xre, m.w, fmaf( xim, m.z, ai[2 * j4 + 1]));
            }
        }
        #pragma unroll
        for (int j = 0; j < 16; j++) { vr[j] = ar[j]; vi[j] = ai[j]; }
    }

    // Final contraction: R14[bits 49..63]  (from L2-resident table).
    {
        const float4* R = (const float4*)(g_R14 + (size_t)(bits >> 49) * 16);
        float sr = 0.f, si = 0.f;
        #pragma unroll
        for (int q = 0; q < 8; q++) {
            float4 v = R[q];   // (Rr[2q], Ri[2q], Rr[2q+1], Ri[2q+1])
            sr = fmaf(vr[2 * q],     v.x, fmaf(-vi[2 * q],     v.y, sr));
            si = fmaf(vr[2 * q],     v.y, fmaf( vi[2 * q],     v.x, si));
            sr = fmaf(vr[2 * q + 1], v.z, fmaf(-vi[2 * q + 1], v.w, sr));
            si = fmaf(vr[2 * q + 1], v.w, fmaf( vi[2 * q + 1], v.z, si));
        }
        out[n]     = sr;
        out[N + n] = si;
    }
}

// ------------------------------ launch -------------------------------------

extern "C" void kernel_launch(void* const* d_in, const int* in_sizes, int n_in,
                              void* d_out, int out_size) {
    const int*   x       = (const int*)  d_in[0];
    const float* left_r  = (const float*)d_in[1];
    const float* left_i  = (const float*)d_in[2];
    const float* bulk_r  = (const float*)d_in[3];
    const float* bulk_i  = (const float*)d_in[4];
    const float* right_r = (const float*)d_in[5];
    const float* right_i = (const float*)d_in[6];

    int N = in_sizes[0] / 64;   // 131072

    k_g2<<<4, 256>>>(bulk_r, bulk_i);
    k_g4<<<16, 256>>>();
    k_g6<<<64, 256>>>();
    k_lg6<<<2, 1024>>>(left_r, left_i);
    k_lg12<<<512, 256>>>();
    k_r2<<<1, 128>>>(right_r, right_i);
    k_r8<<<32, 256>>>();
    k_r14<<<2048, 256>>>();

    cudaFuncSetAttribute(mps_main, cudaFuncAttributeMaxDynamicSharedMemorySize,
                         SMEM_FLOATS * (int)sizeof(float));
    mps_main<<<N / 512, 512, SMEM_FLOATS * sizeof(float)>>>(x, (float*)d_out, N);
}